// round 2
// baseline (speedup 1.0000x reference)
#include <cuda_runtime.h>
#include <cuda_bf16.h>

#define N_NODES 100000
#define N_EDGES 1600000
#define DIM 128
#define NB_SCAN ((N_NODES + 1023) / 1024)   // 98 scan blocks

// ---------------- device scratch (no allocs allowed) ----------------
__device__ float g_h[(size_t)N_NODES * DIM];   // h = x @ W^T   (51.2 MB)
__device__ int   g_cnt[N_NODES];               // histogram, then scatter cursor, then segment END
__device__ int   g_off[N_NODES];               // CSR start offsets
__device__ int   g_bsum[NB_SCAN];              // per-block scan sums
__device__ int   g_srcv[N_EDGES];              // dst-sorted src indices
__device__ float g_valv[N_EDGES];              // dst-sorted edge values

// ---------------------------------------------------------------------------
// Zero the per-node counters (out is fully overwritten by reduce_kernel).
// ---------------------------------------------------------------------------
__global__ void zero_cnt_kernel() {
    int i = blockIdx.x * blockDim.x + threadIdx.x;
    if (i < N_NODES) g_cnt[i] = 0;
}

// ---------------------------------------------------------------------------
// GEMM: g_h[n][o] = sum_k x[n][k] * W[o][k], using packed fma.rn.f32x2.
// Accumulator packs (even-k, odd-k) partial sums in a b64; both halves come
// straight out of the .128 loads (no packing MOVs). Summed in the epilogue.
// ---------------------------------------------------------------------------
__device__ __forceinline__ void fma2(unsigned long long& acc,
                                     unsigned long long a,
                                     unsigned long long b) {
    asm("fma.rn.f32x2 %0, %1, %2, %0;" : "+l"(acc) : "l"(a), "l"(b));
}

__global__ __launch_bounds__(256) void gemm_kernel(const float* __restrict__ x,
                                                   const float* __restrict__ W) {
    extern __shared__ float w_s[]; // [128][132] padded
    const int tid = threadIdx.x;

    for (int idx = tid; idx < 128 * 32; idx += 256) {
        int row = idx >> 5;
        int c4  = idx & 31;
        float4 v = *reinterpret_cast<const float4*>(W + row * 128 + c4 * 4);
        *reinterpret_cast<float4*>(w_s + row * 132 + c4 * 4) = v;
    }
    __syncthreads();

    const int cid = tid & 31;
    const int rid = tid >> 5;
    const long row0 = (long)blockIdx.x * 64 + (long)rid * 8;

    const float* xp[8];
#pragma unroll
    for (int r = 0; r < 8; r++) {
        long row = row0 + r;
        if (row > N_NODES - 1) row = N_NODES - 1;  // clamp loads; writes guarded
        xp[r] = x + row * DIM;
    }

    unsigned long long acc2[8][4];
#pragma unroll
    for (int r = 0; r < 8; r++)
#pragma unroll
        for (int j = 0; j < 4; j++) acc2[r][j] = 0ull;  // bit pattern of (0.f,0.f)

#pragma unroll 4
    for (int k4 = 0; k4 < 32; ++k4) {
        ulonglong2 wp[4];
#pragma unroll
        for (int j = 0; j < 4; j++)
            wp[j] = *reinterpret_cast<const ulonglong2*>(w_s + (cid + 32 * j) * 132 + k4 * 4);
#pragma unroll
        for (int r = 0; r < 8; r++) {
            ulonglong2 xv = *reinterpret_cast<const ulonglong2*>(xp[r] + k4 * 4);
#pragma unroll
            for (int j = 0; j < 4; j++) {
                fma2(acc2[r][j], xv.x, wp[j].x);
                fma2(acc2[r][j], xv.y, wp[j].y);
            }
        }
    }

#pragma unroll
    for (int r = 0; r < 8; r++) {
        long row = row0 + r;
        if (row < N_NODES) {
            float* hp = g_h + row * DIM;
#pragma unroll
            for (int j = 0; j < 4; j++) {
                unsigned long long u = acc2[r][j];
                float lo = __uint_as_float((unsigned)(u & 0xffffffffu));
                float hi = __uint_as_float((unsigned)(u >> 32));
                hp[cid + 32 * j] = lo + hi;
            }
        }
    }
}

// ---------------------------------------------------------------------------
// CSR build: histogram -> scan -> scatter
// ---------------------------------------------------------------------------
__global__ void hist_kernel(const int* __restrict__ dst) {
    int e = blockIdx.x * blockDim.x + threadIdx.x;
    if (e < N_EDGES) atomicAdd(&g_cnt[__ldg(dst + e)], 1);
}

// Pass A: per-block (1024 elems) exclusive scan, block totals to g_bsum.
__global__ __launch_bounds__(256) void scan_a_kernel() {
    __shared__ int sh[256];
    const int b = blockIdx.x, t = threadIdx.x;
    const int base = b * 1024 + t * 4;

    int v[4], tsum = 0;
#pragma unroll
    for (int k = 0; k < 4; k++) {
        int idx = base + k;
        v[k] = (idx < N_NODES) ? g_cnt[idx] : 0;
        tsum += v[k];
    }
    sh[t] = tsum;
    __syncthreads();
    // Hillis-Steele inclusive scan
    for (int off = 1; off < 256; off <<= 1) {
        int xv = (t >= off) ? sh[t - off] : 0;
        __syncthreads();
        sh[t] += xv;
        __syncthreads();
    }
    int run = sh[t] - tsum;  // exclusive
    if (t == 255) g_bsum[b] = sh[255];
#pragma unroll
    for (int k = 0; k < 4; k++) {
        int idx = base + k;
        if (idx < N_NODES) g_off[idx] = run;
        run += v[k];
    }
}

// Pass B: add block-sum prefix; also initialize scatter cursor (g_cnt = off).
__global__ __launch_bounds__(256) void scan_b_kernel() {
    __shared__ int sh[256];
    const int b = blockIdx.x, t = threadIdx.x;
    sh[t] = (t < b) ? g_bsum[t] : 0;
    __syncthreads();
    for (int off = 128; off > 0; off >>= 1) {
        if (t < off) sh[t] += sh[t + off];
        __syncthreads();
    }
    const int pre = sh[0];
    const int base = b * 1024 + t * 4;
#pragma unroll
    for (int k = 0; k < 4; k++) {
        int idx = base + k;
        if (idx < N_NODES) {
            int o = g_off[idx] + pre;
            g_off[idx] = o;
            g_cnt[idx] = o;  // cursor; after scatter it equals segment end
        }
    }
}

__global__ void scatter_kernel(const float* __restrict__ vals,
                               const int* __restrict__ src,
                               const int* __restrict__ dst) {
    int e = blockIdx.x * blockDim.x + threadIdx.x;
    if (e >= N_EDGES) return;
    int d = __ldg(dst + e);
    int pos = atomicAdd(&g_cnt[d], 1);
    g_srcv[pos] = __ldg(src + e);
    g_valv[pos] = __ldg(vals + e);
}

// ---------------------------------------------------------------------------
// Per-node reduce: warp per node, lane l covers floats [4l, 4l+4).
// Gathers h[src] (coalesced 512B/row, L2-resident), accumulates in registers,
// writes out once. No fp atomics anywhere.
// ---------------------------------------------------------------------------
__global__ __launch_bounds__(256) void reduce_kernel(float* __restrict__ out) {
    const int n    = blockIdx.x * 8 + (threadIdx.x >> 5);
    const int lane = threadIdx.x & 31;
    if (n >= N_NODES) return;

    int e   = g_off[n];
    int end = g_cnt[n];  // post-scatter cursor == segment end

    float4 acc = make_float4(0.f, 0.f, 0.f, 0.f);
    for (; e + 1 < end; e += 2) {
        int   s0 = __ldg(g_srcv + e);
        int   s1 = __ldg(g_srcv + e + 1);
        float v0 = __ldg(g_valv + e);
        float v1 = __ldg(g_valv + e + 1);
        float4 h0 = *reinterpret_cast<const float4*>(g_h + (long)s0 * DIM + lane * 4);
        float4 h1 = *reinterpret_cast<const float4*>(g_h + (long)s1 * DIM + lane * 4);
        acc.x += v0 * h0.x + v1 * h1.x;
        acc.y += v0 * h0.y + v1 * h1.y;
        acc.z += v0 * h0.z + v1 * h1.z;
        acc.w += v0 * h0.w + v1 * h1.w;
    }
    if (e < end) {
        int   s0 = __ldg(g_srcv + e);
        float v0 = __ldg(g_valv + e);
        float4 h0 = *reinterpret_cast<const float4*>(g_h + (long)s0 * DIM + lane * 4);
        acc.x += v0 * h0.x;
        acc.y += v0 * h0.y;
        acc.z += v0 * h0.z;
        acc.w += v0 * h0.w;
    }
    *reinterpret_cast<float4*>(out + (long)n * DIM + lane * 4) = acc;
}

// ---------------------------------------------------------------------------
// Launch. Inputs: x, W, vals, src, dst. Output float32 [N_NODES, DIM].
// ---------------------------------------------------------------------------
extern "C" void kernel_launch(void* const* d_in, const int* in_sizes, int n_in,
                              void* d_out, int out_size) {
    const float* x    = (const float*)d_in[0];
    const float* W    = (const float*)d_in[1];
    const float* vals = (const float*)d_in[2];
    const int*   src  = (const int*)d_in[3];
    const int*   dst  = (const int*)d_in[4];
    float*       out  = (float*)d_out;

    const int smem = 128 * 132 * sizeof(float);
    cudaFuncSetAttribute(gemm_kernel, cudaFuncAttributeMaxDynamicSharedMemorySize, smem);

    const int EB = (N_EDGES + 255) / 256;

    zero_cnt_kernel<<<(N_NODES + 255) / 256, 256>>>();
    gemm_kernel<<<(N_NODES + 63) / 64, 256, smem>>>(x, W);
    hist_kernel<<<EB, 256>>>(dst);
    scan_a_kernel<<<NB_SCAN, 256>>>();
    scan_b_kernel<<<NB_SCAN, 256>>>();
    scatter_kernel<<<EB, 256>>>(vals, src, dst);
    reduce_kernel<<<(N_NODES + 7) / 8, 256>>>(out);
}